// round 15
// baseline (speedup 1.0000x reference)
#include <cuda_runtime.h>
#include <cuda_bf16.h>

// CRF NLL, B x T x K=9 (START=7, STOP=8), 7 live states.
// fused_kernel: even blocks = one sentence's 16 operator chunks (16 groups x
//               8 lanes, f32x2-packed, NCH=16, C=128; chunk 0 covers steps
//               [1,C), initial vector handled in combine). Groups in a warp
//               are consecutive chunks of the SAME sentence -> natural
//               length affinity, no permutation needed.
//               odd blocks = gold score for one sentence (memory-bound,
//               hides under chunk compute).
// combine_kernel: thread-per-sentence: build init vector from feat[b][0][:],
//               fold all chunk operators (coalesced float4 loads), fused mean.

#define NCH 16
#define NS  7
#define KK  9
#define MAXB 2048

typedef unsigned long long ull;

// float4 quad (c, qf, b) at float index (c*16 + qf)*(4*B) + b*4.
// qf = 2*s -> column s j=0..3 ; qf = 2*s+1 -> column s j=4..6, w: s==0?csmax:0
__device__ float g_scratch[(size_t)NCH * 16 * 4 * MAXB];
__device__ float g_gold[MAXB];
__device__ float g_accum = 0.f;
__device__ int   g_done  = 0;

__device__ __forceinline__ ull pk2(float x, float y) {
    ull d; asm("mov.b64 %0, {%1,%2};" : "=l"(d) : "f"(x), "f"(y)); return d;
}
__device__ __forceinline__ void upk2(ull d, float& x, float& y) {
    asm("mov.b64 {%0,%1}, %2;" : "=f"(x), "=f"(y) : "l"(d));
}
__device__ __forceinline__ ull ffma2(ull a, ull b, ull c) {
    ull d; asm("fma.rn.f32x2 %0, %1, %2, %3;" : "=l"(d) : "l"(a), "l"(b), "l"(c));
    return d;
}
__device__ __forceinline__ ull fmul2(ull a, ull b) {
    ull d; asm("mul.rn.f32x2 %0, %1, %2;" : "=l"(d) : "l"(a), "l"(b)); return d;
}

// ---------------------------------------------------------------------------
// Fused chunk + gold kernel. Even blocks: 16 operator chunks of sentence
// (blockIdx.x>>1). Odd blocks: gold score for sentence (blockIdx.x>>1).
// ---------------------------------------------------------------------------
__global__ void __launch_bounds__(128) fused_kernel(
    const float* __restrict__ feats, const float* __restrict__ trans,
    const int* __restrict__ tags, const int* __restrict__ lengths,
    int B, int T, int C)
{
    __shared__ float s_tr[KK * KK];
    __shared__ float s_et[NS * NS];
    __shared__ float s_red[4];
    int tid = threadIdx.x;
    if (tid < KK * KK) s_tr[tid] = trans[tid];
    __syncthreads();

    int b = blockIdx.x >> 1;
    if (b >= B) return;
    int L = lengths[b];

    if (blockIdx.x & 1) {
        // ================= GOLD path: one sentence, 128 threads ===========
        const int*   tgb = tags  + (size_t)b * T;
        const float* fb  = feats + (size_t)b * T * KK;

        float acc = 0.f;
        for (int base = 0; base < L; base += 8 * 128) {
            int tg[8], pv[8];
            #pragma unroll
            for (int i = 0; i < 8; i++) {
                int t = base + tid + (i << 7);
                bool a = t < L;
                tg[i] = a ? __ldg(&tgb[t]) : 0;
                pv[i] = a ? ((t == 0) ? 7 : __ldg(&tgb[t - 1])) : 0;
            }
            #pragma unroll
            for (int i = 0; i < 8; i++) {
                int t = base + tid + (i << 7);
                if (t < L)
                    acc += s_tr[tg[i] * KK + pv[i]] +
                           __ldg(&fb[(size_t)t * KK + tg[i]]);
            }
        }

        int lane = tid & 31, wid = tid >> 5;
        #pragma unroll
        for (int d = 16; d; d >>= 1) acc += __shfl_xor_sync(0xFFFFFFFFu, acc, d);
        if (lane == 0) s_red[wid] = acc;
        __syncthreads();
        if (tid == 0) {
            float tot = s_red[0] + s_red[1] + s_red[2] + s_red[3];
            int last = __ldg(&tgb[L - 1]);
            g_gold[b] = tot + s_tr[8 * KK + last];
        }
        return;
    }

    // ============ CHUNK path: 16 operator chunks of one sentence ==========
    if (tid < NS * NS) s_et[tid] = __expf(s_tr[(tid / NS) * KK + (tid % NS)]);
    __syncthreads();

    int c = tid >> 3;                    // chunk 0..15
    int lane = tid & 7;
    unsigned grpw  = (unsigned)(tid & 31) & 24u;
    unsigned mask8 = 0xFFu << grpw;

    int t0 = (c == 0) ? 1 : c * C;       // chunk 0 covers [1, C)
    int t1 = min(L, (c + 1) * C);
    if (c > 0 && c * C >= L) return;     // inactive chunk (never read)

    const float* fb = feats + (size_t)b * T * KK;

    // Row pairs (0,1),(2,3),(4,5),(6,6): etp[p][i] = (et[j0][i], et[j1][i])
    ull etp[4][NS];
    #pragma unroll
    for (int p = 0; p < 4; p++) {
        int j0 = 2 * p, j1 = (2 * p + 1 < NS) ? 2 * p + 1 : NS - 1;
        #pragma unroll
        for (int i = 0; i < NS; i++)
            etp[p][i] = pk2(s_et[j0 * NS + i], s_et[j1 * NS + i]);
    }

    float v[NS];
    #pragma unroll
    for (int j = 0; j < NS; j++) v[j] = (j == lane) ? 1.f : 0.f;   // lane7: 0s
    float csc = 0.f;

    int rc = 0;
    for (int t = t0; t < t1; ++t) {
        float fv = 0.f;
        if (lane < NS) fv = __ldg(&fb[t * KK + lane]);
        float efl = __expf(fv);
        float e0 = __shfl_sync(mask8, efl, grpw + 0);
        float e1 = __shfl_sync(mask8, efl, grpw + 1);
        float e2 = __shfl_sync(mask8, efl, grpw + 2);
        float e3 = __shfl_sync(mask8, efl, grpw + 3);
        float e4 = __shfl_sync(mask8, efl, grpw + 4);
        float e5 = __shfl_sync(mask8, efl, grpw + 5);
        float e6 = __shfl_sync(mask8, efl, grpw + 6);
        ull ep0 = pk2(e0, e1);
        ull ep1 = pk2(e2, e3);
        ull ep2 = pk2(e4, e5);
        ull ep3 = pk2(e6, 0.f);

        ull dv0 = pk2(v[0], v[0]);
        ull dv1 = pk2(v[1], v[1]);
        ull dv2 = pk2(v[2], v[2]);
        ull dv3 = pk2(v[3], v[3]);
        ull dv4 = pk2(v[4], v[4]);
        ull dv5 = pk2(v[5], v[5]);
        ull dv6 = pk2(v[6], v[6]);

        ull a0 = fmul2(etp[0][0], dv0);
        ull a1 = fmul2(etp[1][0], dv0);
        ull a2 = fmul2(etp[2][0], dv0);
        ull a3 = fmul2(etp[3][0], dv0);
        a0 = ffma2(etp[0][1], dv1, a0); a1 = ffma2(etp[1][1], dv1, a1);
        a2 = ffma2(etp[2][1], dv1, a2); a3 = ffma2(etp[3][1], dv1, a3);
        a0 = ffma2(etp[0][2], dv2, a0); a1 = ffma2(etp[1][2], dv2, a1);
        a2 = ffma2(etp[2][2], dv2, a2); a3 = ffma2(etp[3][2], dv2, a3);
        a0 = ffma2(etp[0][3], dv3, a0); a1 = ffma2(etp[1][3], dv3, a1);
        a2 = ffma2(etp[2][3], dv3, a2); a3 = ffma2(etp[3][3], dv3, a3);
        a0 = ffma2(etp[0][4], dv4, a0); a1 = ffma2(etp[1][4], dv4, a1);
        a2 = ffma2(etp[2][4], dv4, a2); a3 = ffma2(etp[3][4], dv4, a3);
        a0 = ffma2(etp[0][5], dv5, a0); a1 = ffma2(etp[1][5], dv5, a1);
        a2 = ffma2(etp[2][5], dv5, a2); a3 = ffma2(etp[3][5], dv5, a3);
        a0 = ffma2(etp[0][6], dv6, a0); a1 = ffma2(etp[1][6], dv6, a1);
        a2 = ffma2(etp[2][6], dv6, a2); a3 = ffma2(etp[3][6], dv6, a3);

        a0 = fmul2(a0, ep0); a1 = fmul2(a1, ep1);
        a2 = fmul2(a2, ep2); a3 = fmul2(a3, ep3);

        float dead;
        upk2(a0, v[0], v[1]); upk2(a1, v[2], v[3]);
        upk2(a2, v[4], v[5]); upk2(a3, v[6], dead);

        if (++rc == 4) {
            rc = 0;
            float mm = v[0];
            #pragma unroll
            for (int j = 1; j < NS; j++) mm = fmaxf(mm, v[j]);
            mm = fmaxf(mm, 1e-30f);
            float inv = __fdividef(1.f, mm);
            #pragma unroll
            for (int j = 0; j < NS; j++) v[j] *= inv;
            csc += __logf(mm);
        }
    }
    float mm = v[0];
    #pragma unroll
    for (int j = 1; j < NS; j++) mm = fmaxf(mm, v[j]);
    mm = fmaxf(mm, 1e-30f);
    float inv = __fdividef(1.f, mm);
    #pragma unroll
    for (int j = 0; j < NS; j++) v[j] *= inv;
    csc += __logf(mm);

    // Joint column scaling: one csmax per chunk; columns pre-weighted.
    float cx = (lane < NS) ? csc : -1e30f;
    #pragma unroll
    for (int d = 1; d < 8; d <<= 1)
        cx = fmaxf(cx, __shfl_xor_sync(mask8, cx, d));
    float wsc = __expf(csc - cx);

    if (lane < NS) {
        float4 q0 = make_float4(v[0] * wsc, v[1] * wsc, v[2] * wsc, v[3] * wsc);
        float4 q1 = make_float4(v[4] * wsc, v[5] * wsc, v[6] * wsc,
                                (lane == 0) ? cx : 0.f);
        size_t fbase = ((size_t)c * 16 + lane * 2) * 4 * B + (size_t)b * 4;
        *(float4*)&g_scratch[fbase]         = q0;
        *(float4*)&g_scratch[fbase + 4 * B] = q1;
    }
}

// ---------------------------------------------------------------------------
// Thread-per-sentence: build init vector from feat[b][0][:] + trans[:,START],
// fold chunk operators (coalesced float4s), finish scores, fused mean.
// ---------------------------------------------------------------------------
__global__ void __launch_bounds__(128) combine_kernel(
    const float* __restrict__ feats, const float* __restrict__ trans,
    const int* __restrict__ lengths, float* __restrict__ out,
    int B, int T, int C)
{
    int tid = threadIdx.x;
    int b = blockIdx.x * blockDim.x + tid;

    if (b < B) {
        int L = lengths[b];
        const float* fb = feats + (size_t)b * T * KK;

        // init: alpha after step 0 = trans[j,START] + feat[0,j]
        float x[NS];
        #pragma unroll
        for (int j = 0; j < NS; j++)
            x[j] = __ldg(&trans[j * KK + 7]) + __ldg(&fb[j]);
        float m = x[0];
        #pragma unroll
        for (int j = 1; j < NS; j++) m = fmaxf(m, x[j]);
        float v[NS];
        #pragma unroll
        for (int j = 0; j < NS; j++) v[j] = __expf(x[j] - m);
        float sc = m;

        float est[NS];
        #pragma unroll
        for (int j = 0; j < NS; j++) est[j] = __expf(__ldg(&trans[8 * KK + j]));

        for (int c = 0; c < NCH && (c == 0 || c * C < L); ++c) {
            size_t cb = ((size_t)c * 16) * 4 * B + (size_t)b * 4;
            float4 ma[NS], mb[NS];
            #pragma unroll
            for (int s = 0; s < NS; ++s) {
                ma[s] = *(const float4*)&g_scratch[cb + (size_t)(2 * s) * 4 * B];
                mb[s] = *(const float4*)&g_scratch[cb + (size_t)(2 * s + 1) * 4 * B];
            }
            float csmax = mb[0].w;

            float n0 = 0.f, n1 = 0.f, n2 = 0.f, n3 = 0.f, n4 = 0.f, n5 = 0.f, n6 = 0.f;
            #pragma unroll
            for (int s = 0; s < NS; ++s) {
                float vs = v[s];
                n0 = fmaf(ma[s].x, vs, n0);
                n1 = fmaf(ma[s].y, vs, n1);
                n2 = fmaf(ma[s].z, vs, n2);
                n3 = fmaf(ma[s].w, vs, n3);
                n4 = fmaf(mb[s].x, vs, n4);
                n5 = fmaf(mb[s].y, vs, n5);
                n6 = fmaf(mb[s].z, vs, n6);
            }
            float mm = fmaxf(fmaxf(fmaxf(n0, n1), fmaxf(n2, n3)),
                             fmaxf(fmaxf(n4, n5), n6));
            mm = fmaxf(mm, 1e-30f);
            float inv = __fdividef(1.f, mm);
            v[0] = n0 * inv; v[1] = n1 * inv; v[2] = n2 * inv; v[3] = n3 * inv;
            v[4] = n4 * inv; v[5] = n5 * inv; v[6] = n6 * inv;
            sc += csmax + __logf(mm);
        }

        float acc = 0.f;
        #pragma unroll
        for (int j = 0; j < NS; j++) acc = fmaf(v[j], est[j], acc);
        float fwd = sc + __logf(acc);

        atomicAdd(&g_accum, fwd - g_gold[b]);
        __threadfence();
    }

    __syncthreads();
    if (tid == 0) {
        __threadfence();
        int old = atomicAdd(&g_done, 1);
        if (old == (int)gridDim.x - 1) {
            __threadfence();
            float tot = *((volatile float*)&g_accum);
            out[0] = tot / (float)B;
            *((volatile float*)&g_accum) = 0.f;
            __threadfence();
            *((volatile int*)&g_done) = 0;
        }
    }
}

extern "C" void kernel_launch(void* const* d_in, const int* in_sizes, int n_in,
                              void* d_out, int out_size)
{
    const float* feats   = (const float*)d_in[0];
    const float* trans   = (const float*)d_in[1];
    const int*   tags    = (const int*)d_in[2];
    const int*   lengths = (const int*)d_in[3];

    int B = in_sizes[3];
    int T = in_sizes[2] / B;
    int C = (T + NCH - 1) / NCH;

    // Even blocks: chunk scan (one sentence's 16 chunks). Odd: gold.
    fused_kernel<<<2 * B, 128>>>(feats, trans, tags, lengths, B, T, C);
    combine_kernel<<<(B + 127) / 128, 128>>>(feats, trans, lengths,
                                             (float*)d_out, B, T, C);
}

// round 16
// speedup vs baseline: 1.2117x; 1.2117x over previous
#include <cuda_runtime.h>
#include <cuda_bf16.h>

// CRF NLL, B x T x K=9 (START=7, STOP=8), 7 live states.
// ONE kernel, 2B blocks:
//  even block 2b : all 16 operator chunks of sentence b (16 groups x 8 lanes,
//                  f32x2-packed, NCH=16, C=128; chunk 0 covers steps [1,C)).
//                  Operators stay in SMEM; after __syncthreads, warp-0 lanes
//                  0..7 build the init vector and fold the operators
//                  (uniform trip count — one sentence per block), then
//                  atomicAdd(+fwd).
//  odd block 2b+1: gold path score for sentence b (memory-bound, hides under
//                  chunk compute); atomicAdd(-gold).
// A done-counter across all 2B blocks writes mean and resets accumulators.

#define NCH 16
#define NS  7
#define KK  9

typedef unsigned long long ull;

__device__ float g_accum = 0.f;
__device__ int   g_done  = 0;

__device__ __forceinline__ ull pk2(float x, float y) {
    ull d; asm("mov.b64 %0, {%1,%2};" : "=l"(d) : "f"(x), "f"(y)); return d;
}
__device__ __forceinline__ void upk2(ull d, float& x, float& y) {
    asm("mov.b64 {%0,%1}, %2;" : "=f"(x), "=f"(y) : "l"(d));
}
__device__ __forceinline__ ull ffma2(ull a, ull b, ull c) {
    ull d; asm("fma.rn.f32x2 %0, %1, %2, %3;" : "=l"(d) : "l"(a), "l"(b), "l"(c));
    return d;
}
__device__ __forceinline__ ull fmul2(ull a, ull b) {
    ull d; asm("mul.rn.f32x2 %0, %1, %2;" : "=l"(d) : "l"(a), "l"(b)); return d;
}

__global__ void __launch_bounds__(128) crf_kernel(
    const float* __restrict__ feats, const float* __restrict__ trans,
    const int* __restrict__ tags, const int* __restrict__ lengths,
    float* __restrict__ out, int B, int T, int C)
{
    __shared__ float s_tr[KK * KK];
    __shared__ float s_et[NS * NS];
    __shared__ float s_op[NCH * 64];   // per-chunk operator: [c*64 + s*8 + j],
                                       // slot c*64+7 = csmax
    __shared__ float s_red[4];
    int tid = threadIdx.x;
    if (tid < KK * KK) s_tr[tid] = trans[tid];
    __syncthreads();

    int b = blockIdx.x >> 1;
    int L = lengths[b];
    const float* fb = feats + (size_t)b * T * KK;

    if (blockIdx.x & 1) {
        // ================= GOLD block: one sentence, 128 threads ==========
        const int* tgb = tags + (size_t)b * T;

        float acc = 0.f;
        for (int base = 0; base < L; base += 8 * 128) {
            int tg[8], pv[8];
            #pragma unroll
            for (int i = 0; i < 8; i++) {
                int t = base + tid + (i << 7);
                bool a = t < L;
                tg[i] = a ? __ldg(&tgb[t]) : 0;
                pv[i] = a ? ((t == 0) ? 7 : __ldg(&tgb[t - 1])) : 0;
            }
            #pragma unroll
            for (int i = 0; i < 8; i++) {
                int t = base + tid + (i << 7);
                if (t < L)
                    acc += s_tr[tg[i] * KK + pv[i]] +
                           __ldg(&fb[(size_t)t * KK + tg[i]]);
            }
        }

        int lane = tid & 31, wid = tid >> 5;
        #pragma unroll
        for (int d = 16; d; d >>= 1) acc += __shfl_xor_sync(0xFFFFFFFFu, acc, d);
        if (lane == 0) s_red[wid] = acc;
        __syncthreads();
        if (tid == 0) {
            float tot = s_red[0] + s_red[1] + s_red[2] + s_red[3];
            int last = __ldg(&tgb[L - 1]);
            atomicAdd(&g_accum, -(tot + s_tr[8 * KK + last]));
            __threadfence();
        }
    } else {
        // =========== CHUNK block: 16 operator chunks + in-block fold ======
        if (tid < NS * NS) s_et[tid] = __expf(s_tr[(tid / NS) * KK + (tid % NS)]);
        __syncthreads();

        int c = tid >> 3;                  // chunk 0..15
        int lane = tid & 7;
        unsigned grpw  = (unsigned)(tid & 31) & 24u;
        unsigned mask8 = 0xFFu << grpw;

        bool active = (c == 0) || (c * C < L);
        if (active) {
            int t0 = (c == 0) ? 1 : c * C;     // chunk 0 covers [1, C)
            int t1 = min(L, (c + 1) * C);

            ull etp[4][NS];
            #pragma unroll
            for (int p = 0; p < 4; p++) {
                int j0 = 2 * p, j1 = (2 * p + 1 < NS) ? 2 * p + 1 : NS - 1;
                #pragma unroll
                for (int i = 0; i < NS; i++)
                    etp[p][i] = pk2(s_et[j0 * NS + i], s_et[j1 * NS + i]);
            }

            float v[NS];
            #pragma unroll
            for (int j = 0; j < NS; j++) v[j] = (j == lane) ? 1.f : 0.f;
            float csc = 0.f;

            int rc = 0;
            for (int t = t0; t < t1; ++t) {
                float fv = 0.f;
                if (lane < NS) fv = __ldg(&fb[t * KK + lane]);
                float efl = __expf(fv);
                float e0 = __shfl_sync(mask8, efl, grpw + 0);
                float e1 = __shfl_sync(mask8, efl, grpw + 1);
                float e2 = __shfl_sync(mask8, efl, grpw + 2);
                float e3 = __shfl_sync(mask8, efl, grpw + 3);
                float e4 = __shfl_sync(mask8, efl, grpw + 4);
                float e5 = __shfl_sync(mask8, efl, grpw + 5);
                float e6 = __shfl_sync(mask8, efl, grpw + 6);
                ull ep0 = pk2(e0, e1);
                ull ep1 = pk2(e2, e3);
                ull ep2 = pk2(e4, e5);
                ull ep3 = pk2(e6, 0.f);

                ull dv0 = pk2(v[0], v[0]);
                ull dv1 = pk2(v[1], v[1]);
                ull dv2 = pk2(v[2], v[2]);
                ull dv3 = pk2(v[3], v[3]);
                ull dv4 = pk2(v[4], v[4]);
                ull dv5 = pk2(v[5], v[5]);
                ull dv6 = pk2(v[6], v[6]);

                ull a0 = fmul2(etp[0][0], dv0);
                ull a1 = fmul2(etp[1][0], dv0);
                ull a2 = fmul2(etp[2][0], dv0);
                ull a3 = fmul2(etp[3][0], dv0);
                a0 = ffma2(etp[0][1], dv1, a0); a1 = ffma2(etp[1][1], dv1, a1);
                a2 = ffma2(etp[2][1], dv1, a2); a3 = ffma2(etp[3][1], dv1, a3);
                a0 = ffma2(etp[0][2], dv2, a0); a1 = ffma2(etp[1][2], dv2, a1);
                a2 = ffma2(etp[2][2], dv2, a2); a3 = ffma2(etp[3][2], dv2, a3);
                a0 = ffma2(etp[0][3], dv3, a0); a1 = ffma2(etp[1][3], dv3, a1);
                a2 = ffma2(etp[2][3], dv3, a2); a3 = ffma2(etp[3][3], dv3, a3);
                a0 = ffma2(etp[0][4], dv4, a0); a1 = ffma2(etp[1][4], dv4, a1);
                a2 = ffma2(etp[2][4], dv4, a2); a3 = ffma2(etp[3][4], dv4, a3);
                a0 = ffma2(etp[0][5], dv5, a0); a1 = ffma2(etp[1][5], dv5, a1);
                a2 = ffma2(etp[2][5], dv5, a2); a3 = ffma2(etp[3][5], dv5, a3);
                a0 = ffma2(etp[0][6], dv6, a0); a1 = ffma2(etp[1][6], dv6, a1);
                a2 = ffma2(etp[2][6], dv6, a2); a3 = ffma2(etp[3][6], dv6, a3);

                a0 = fmul2(a0, ep0); a1 = fmul2(a1, ep1);
                a2 = fmul2(a2, ep2); a3 = fmul2(a3, ep3);

                float dead;
                upk2(a0, v[0], v[1]); upk2(a1, v[2], v[3]);
                upk2(a2, v[4], v[5]); upk2(a3, v[6], dead);

                if (++rc == 4) {
                    rc = 0;
                    float mm = v[0];
                    #pragma unroll
                    for (int j = 1; j < NS; j++) mm = fmaxf(mm, v[j]);
                    mm = fmaxf(mm, 1e-30f);
                    float inv = __fdividef(1.f, mm);
                    #pragma unroll
                    for (int j = 0; j < NS; j++) v[j] *= inv;
                    csc += __logf(mm);
                }
            }
            float mm = v[0];
            #pragma unroll
            for (int j = 1; j < NS; j++) mm = fmaxf(mm, v[j]);
            mm = fmaxf(mm, 1e-30f);
            float inv = __fdividef(1.f, mm);
            #pragma unroll
            for (int j = 0; j < NS; j++) v[j] *= inv;
            csc += __logf(mm);

            // Joint column scaling: one csmax per chunk, columns pre-weighted.
            float cx = (lane < NS) ? csc : -1e30f;
            #pragma unroll
            for (int d = 1; d < 8; d <<= 1)
                cx = fmaxf(cx, __shfl_xor_sync(mask8, cx, d));
            float wsc = __expf(csc - cx);

            if (lane < NS) {
                #pragma unroll
                for (int j = 0; j < NS; j++)
                    s_op[c * 64 + lane * 8 + j] = v[j] * wsc;
            }
            if (lane == 0) s_op[c * 64 + 7] = cx;
        }
        __syncthreads();

        // ---------------- in-block fold: warp 0, lanes 0..7 ---------------
        if (tid < 8) {
            const unsigned m8 = 0xFFu;
            // init vector: alpha after step 0 = trans[j,START] + feat[0,j]
            float fj = (tid < NS) ? __ldg(&fb[tid]) : 0.f;
            float x = (tid < NS) ? (s_tr[tid * KK + 7] + fj) : -1e30f;
            float m = x;
            #pragma unroll
            for (int d = 1; d < 8; d <<= 1)
                m = fmaxf(m, __shfl_xor_sync(m8, m, d));
            float v = (tid < NS) ? __expf(x - m) : 0.f;
            float sc = m;

            for (int cc = 0; cc < NCH && (cc == 0 || cc * C < L); ++cc) {
                float csmax = s_op[cc * 64 + 7];
                float n = 0.f;
                #pragma unroll
                for (int s = 0; s < NS; ++s) {
                    float vs = __shfl_sync(m8, v, s);
                    n = fmaf(s_op[cc * 64 + s * 8 + tid], vs, n);
                }
                if (tid == 7) n = -1e30f;
                float mm = n;
                #pragma unroll
                for (int d = 1; d < 8; d <<= 1)
                    mm = fmaxf(mm, __shfl_xor_sync(m8, mm, d));
                mm = fmaxf(mm, 1e-30f);
                v = (tid < NS) ? n * __fdividef(1.f, mm) : 0.f;
                sc += csmax + __logf(mm);
            }

            float term = (tid < NS) ? v * __expf(s_tr[8 * KK + tid]) : 0.f;
            #pragma unroll
            for (int d = 1; d < 8; d <<= 1)
                term += __shfl_xor_sync(m8, term, d);
            float fwd = sc + __logf(term);
            if (tid == 0) {
                atomicAdd(&g_accum, fwd);
                __threadfence();
            }
        }
    }

    // ---------------- completion counter over all 2B blocks ---------------
    __syncthreads();
    if (tid == 0) {
        __threadfence();
        int old = atomicAdd(&g_done, 1);
        if (old == (int)gridDim.x - 1) {
            __threadfence();
            float tot = *((volatile float*)&g_accum);
            out[0] = tot / (float)B;
            *((volatile float*)&g_accum) = 0.f;
            __threadfence();
            *((volatile int*)&g_done) = 0;
        }
    }
}

extern "C" void kernel_launch(void* const* d_in, const int* in_sizes, int n_in,
                              void* d_out, int out_size)
{
    const float* feats   = (const float*)d_in[0];
    const float* trans   = (const float*)d_in[1];
    const int*   tags    = (const int*)d_in[2];
    const int*   lengths = (const int*)d_in[3];

    int B = in_sizes[3];
    int T = in_sizes[2] / B;
    int C = (T + NCH - 1) / NCH;

    crf_kernel<<<2 * B, 128>>>(feats, trans, tags, lengths,
                               (float*)d_out, B, T, C);
}